// round 11
// baseline (speedup 1.0000x reference)
#include <cuda_runtime.h>
#include <cstdint>

// Problem shape (fixed per reference setup_inputs)
constexpr int Bn = 8;     // batch
constexpr int Tn = 4096;  // xs rows (M)
constexpr int Sn = 256;   // spk rows (N)
constexpr int Dn = 512;   // feature (K)

#define EPS_F 1e-8f

// ---------------------------------------------------------------------------
// Fused kernel: per-batch NT GEMM via TF32 mma.sync + in-register row norms.
// CTA tile 128x128, BK=32, 256 threads (8 warps, 4x2), warp tile 32x64.
// Pair-permuted smem: column (8s + 2t + h) holds k = (8s + t + 4h), so each
// mma fragment k-pair (k, k+4) is ONE LDS.64. SSTR=36 keeps conflicts <=2-way.
// Producer: LDG->cvt.rna->interleaved STS.128, norms fused. 1 sync per tile.
// ---------------------------------------------------------------------------
constexpr int BM = 128, BN = 128, BK = 32;
constexpr int SSTR = 36;                 // padded smem row stride (uint32)
constexpr int NT = Dn / BK;              // 16 k-tiles
constexpr int TILE_U32 = BM * SSTR;      // 4608 uint32 per tile buffer

// dynamic smem layout (bytes)
constexpr int SM_A    = 0;                       // uint32[2][TILE_U32]
constexpr int SM_B    = 2 * TILE_U32 * 4;        // 36864
constexpr int SM_INVX = 4 * TILE_U32 * 4;        // 73728 (128 floats)
constexpr int SM_INVY = SM_INVX + BM * 4;        // 74240 (128 floats)
constexpr int SMEM_TOTAL = SM_INVY + BN * 4;     // 74752

__device__ __forceinline__ uint32_t f2tf(float f) {
    uint32_t u;
    asm("cvt.rna.tf32.f32 %0, %1;" : "=r"(u) : "f"(f));
    return u;
}

__device__ __forceinline__ void mma_tf32(float c[4], const uint32_t a[4],
                                         uint32_t b0, uint32_t b1) {
    asm volatile(
        "mma.sync.aligned.m16n8k8.row.col.f32.tf32.tf32.f32 "
        "{%0,%1,%2,%3}, {%4,%5,%6,%7}, {%8,%9}, {%0,%1,%2,%3};"
        : "+f"(c[0]), "+f"(c[1]), "+f"(c[2]), "+f"(c[3])
        : "r"(a[0]), "r"(a[1]), "r"(a[2]), "r"(a[3]), "r"(b0), "r"(b1));
}

__device__ __forceinline__ float dot4(float4 v) {
    return v.x * v.x + v.y * v.y + v.z * v.z + v.w * v.w;
}

__global__ __launch_bounds__(256, 2)
void cos_gemm_p64(const float* __restrict__ X,
                  const float* __restrict__ Y,
                  float* __restrict__ out) {
    extern __shared__ char smraw[];
    uint32_t* As    = reinterpret_cast<uint32_t*>(smraw + SM_A);   // [2][TILE_U32]
    uint32_t* Bs    = reinterpret_cast<uint32_t*>(smraw + SM_B);
    float*    sinvx = reinterpret_cast<float*>(smraw + SM_INVX);
    float*    sinvy = reinterpret_cast<float*>(smraw + SM_INVY);

    const int tid  = threadIdx.x;
    const int b    = blockIdx.z;
    const int mcta = blockIdx.x * BM;
    const int ncta = blockIdx.y * BN;

    const float* A  = X + (size_t)b * Tn * Dn + (size_t)mcta * Dn;
    const float* Bp = Y + (size_t)b * Sn * Dn + (size_t)ncta * Dn;

    // -------- producer mapping: thread -> (row r, k-octet so) -------------
    // Each thread handles octet so of rows {r, r+64} for both A and B:
    // 8 floats contiguous in gmem (2 float4), stored interleaved in smem.
    const int so = tid & 3;              // k-octet 0..3 (8 floats each)
    const int r  = tid >> 2;             // row 0..63
    const float* gA = A  + (size_t)r * Dn + so * 8;
    const float* gB = Bp + (size_t)r * Dn + so * 8;
    const int sof0 = r * SSTR + so * 8;          // row r
    const int sof1 = (r + 64) * SSTR + so * 8;   // row r+64

    // -------- compute mapping: 8 warps 4x2, warp tile 32x64 ---------------
    const int wid  = tid >> 5;
    const int lane = tid & 31;
    const int wm   = wid >> 1;           // 0..3 (M dir, 32 rows)
    const int wn   = wid & 1;            // 0..1 (N dir, 64 cols)
    const int gid  = lane >> 2;          // 0..7
    const int tig  = lane & 3;           // 0..3

    float acc[2][8][4];
    #pragma unroll
    for (int i = 0; i < 2; ++i)
        #pragma unroll
        for (int j = 0; j < 8; ++j)
            #pragma unroll
            for (int p = 0; p < 4; ++p)
                acc[i][j][p] = 0.0f;

    // norm partials for this thread's rows (r, r+64), octet so slice
    float nx0 = 0.0f, nx1 = 0.0f, ny0 = 0.0f, ny1 = 0.0f;

    // staging: [which(0=A r,1=A r+64,2=B r,3=B r+64)][lo/hi float4]
    float4 st[4][2];

    auto LDG = [&](int kt) {
        const int ko = kt * BK;
        st[0][0] = *reinterpret_cast<const float4*>(gA + ko);
        st[0][1] = *reinterpret_cast<const float4*>(gA + ko + 4);
        st[1][0] = *reinterpret_cast<const float4*>(gA + (size_t)64 * Dn + ko);
        st[1][1] = *reinterpret_cast<const float4*>(gA + (size_t)64 * Dn + ko + 4);
        st[2][0] = *reinterpret_cast<const float4*>(gB + ko);
        st[2][1] = *reinterpret_cast<const float4*>(gB + ko + 4);
        st[3][0] = *reinterpret_cast<const float4*>(gB + (size_t)64 * Dn + ko);
        st[3][1] = *reinterpret_cast<const float4*>(gB + (size_t)64 * Dn + ko + 4);
    };
    // interleaved store: cols 8so..+3 hold k={0,4,1,5}, +4..+7 hold {2,6,3,7}
    auto STS1 = [&](uint32_t* dst, const float4& f0, const float4& f1) {
        uint4 u0, u1;
        u0.x = f2tf(f0.x); u0.y = f2tf(f1.x); u0.z = f2tf(f0.y); u0.w = f2tf(f1.y);
        u1.x = f2tf(f0.z); u1.y = f2tf(f1.z); u1.z = f2tf(f0.w); u1.w = f2tf(f1.w);
        *reinterpret_cast<uint4*>(dst)     = u0;
        *reinterpret_cast<uint4*>(dst + 4) = u1;
    };
    auto STSN = [&](int buf) {
        uint32_t* Ad = As + buf * TILE_U32;
        uint32_t* Bd = Bs + buf * TILE_U32;
        nx0 += dot4(st[0][0]) + dot4(st[0][1]);
        STS1(Ad + sof0, st[0][0], st[0][1]);
        nx1 += dot4(st[1][0]) + dot4(st[1][1]);
        STS1(Ad + sof1, st[1][0], st[1][1]);
        ny0 += dot4(st[2][0]) + dot4(st[2][1]);
        STS1(Bd + sof0, st[2][0], st[2][1]);
        ny1 += dot4(st[3][0]) + dot4(st[3][1]);
        STS1(Bd + sof1, st[3][0], st[3][1]);
    };

    LDG(0);
    STSN(0);
    __syncthreads();

    #pragma unroll 1
    for (int kt = 0; kt < NT; ++kt) {
        const int cur = kt & 1;
        const bool more = (kt + 1 < NT);

        // prefetch next tile to registers; drains under the 128-mma block
        if (more) LDG(kt + 1);

        const uint32_t* __restrict__ Ab = As + cur * TILE_U32;
        const uint32_t* __restrict__ Bb = Bs + cur * TILE_U32;

        #pragma unroll
        for (int s = 0; s < 4; ++s) {    // four k=8 steps per tile
            const int cb = s * 8 + 2 * tig;      // permuted column base
            uint32_t a[2][4];
            #pragma unroll
            for (int i = 0; i < 2; ++i) {
                const int rr = wm * 32 + i * 16 + gid;
                uint2 v0 = *reinterpret_cast<const uint2*>(Ab + rr * SSTR + cb);
                uint2 v1 = *reinterpret_cast<const uint2*>(Ab + (rr + 8) * SSTR + cb);
                a[i][0] = v0.x; a[i][1] = v1.x; a[i][2] = v0.y; a[i][3] = v1.y;
            }
            #pragma unroll
            for (int j = 0; j < 8; ++j) {
                const int n0 = wn * 64 + j * 8 + gid;
                uint2 bv = *reinterpret_cast<const uint2*>(Bb + n0 * SSTR + cb);
                mma_tf32(acc[0][j], a[0], bv.x, bv.y);
                mma_tf32(acc[1][j], a[1], bv.x, bv.y);
            }
        }

        // store into the buffer all warps stopped reading before prev sync
        if (more) STSN((kt + 1) & 1);
        __syncthreads();
    }

    // -------- finish norms: reduce across 4 octet-threads per row ---------
    // threads tid = 4*r + so are contiguous lanes within one warp.
    nx0 += __shfl_xor_sync(0xffffffffu, nx0, 1);
    nx0 += __shfl_xor_sync(0xffffffffu, nx0, 2);
    nx1 += __shfl_xor_sync(0xffffffffu, nx1, 1);
    nx1 += __shfl_xor_sync(0xffffffffu, nx1, 2);
    ny0 += __shfl_xor_sync(0xffffffffu, ny0, 1);
    ny0 += __shfl_xor_sync(0xffffffffu, ny0, 2);
    ny1 += __shfl_xor_sync(0xffffffffu, ny1, 1);
    ny1 += __shfl_xor_sync(0xffffffffu, ny1, 2);
    if (so == 0) {
        sinvx[r]      = 1.0f / fmaxf(sqrtf(nx0), EPS_F);
        sinvx[r + 64] = 1.0f / fmaxf(sqrtf(nx1), EPS_F);
        sinvy[r]      = 1.0f / fmaxf(sqrtf(ny0), EPS_F);
        sinvy[r + 64] = 1.0f / fmaxf(sqrtf(ny1), EPS_F);
    }
    __syncthreads();

    // -------- epilogue: scale by inverse norms, float2 stores --------
    float* C = out + (size_t)b * Tn * Sn + (size_t)mcta * Sn + ncta;

    #pragma unroll
    for (int i = 0; i < 2; ++i) {
        const int rA = wm * 32 + i * 16 + gid;
        const float sx0 = sinvx[rA];
        const float sx1 = sinvx[rA + 8];
        #pragma unroll
        for (int j = 0; j < 8; ++j) {
            const int c0 = wn * 64 + j * 8 + tig * 2;
            const float sy0 = sinvy[c0];
            const float sy1 = sinvy[c0 + 1];
            float2 w;
            w.x = acc[i][j][0] * sx0 * sy0;
            w.y = acc[i][j][1] * sx0 * sy1;
            *reinterpret_cast<float2*>(&C[(size_t)rA * Sn + c0]) = w;
            w.x = acc[i][j][2] * sx1 * sy0;
            w.y = acc[i][j][3] * sx1 * sy1;
            *reinterpret_cast<float2*>(&C[(size_t)(rA + 8) * Sn + c0]) = w;
        }
    }
}

extern "C" void kernel_launch(void* const* d_in, const int* in_sizes, int n_in,
                              void* d_out, int out_size) {
    const float* xs  = (const float*)d_in[0];   // (8, 4096, 512)
    const float* spk = (const float*)d_in[1];   // (8, 256, 512)
    float* out = (float*)d_out;                 // (8, 4096, 256)

    static bool attr_set = false;
    if (!attr_set) {
        cudaFuncSetAttribute(cos_gemm_p64,
                             cudaFuncAttributeMaxDynamicSharedMemorySize,
                             SMEM_TOTAL);
        attr_set = true;
    }

    dim3 grid(Tn / BM, Sn / BN, Bn);            // (32, 2, 8) = 512 CTAs
    cos_gemm_p64<<<grid, 256, SMEM_TOTAL>>>(xs, spk, out);
}

// round 12
// speedup vs baseline: 1.1955x; 1.1955x over previous
#include <cuda_runtime.h>
#include <cstdint>

// Problem shape (fixed per reference setup_inputs)
constexpr int Bn = 8;     // batch
constexpr int Tn = 4096;  // xs rows (M)
constexpr int Sn = 256;   // spk rows (N)
constexpr int Dn = 512;   // feature (K)

#define EPS_F 1e-8f

// ---------------------------------------------------------------------------
// Fused kernel: per-batch NT GEMM via TF32 mma.sync + row norms from smem.
// CTA tile 128x128, BK=32, 256 threads (8 warps, 4x2), warp tile 32x64.
// cp.async.cg 3-stage gmem->smem pipeline of RAW fp32; cvt.rna at fragment
// load. Stride-36 rows -> conflict-free LDS.32. One __syncthreads per k-tile.
// NEW: fragments explicitly double-buffered (a per k-step, b per half-step)
// so each 8-mma batch overlaps the next batch's LDS issue+latency.
// ---------------------------------------------------------------------------
constexpr int BM = 128, BN = 128, BK = 32;
constexpr int SSTR = 36;                  // padded smem row stride (u32)
constexpr int NT = Dn / BK;               // 16 k-tiles
constexpr int STAGES = 3;
constexpr int AU32   = BM * SSTR;         // 4608 u32 per A (or B) tile
constexpr int STAGE_U32 = 2 * AU32;       // A then B
constexpr int SM_INVX = STAGES * STAGE_U32 * 4;      // 110592
constexpr int SM_INVY = SM_INVX + BM * 4;            // 111104
constexpr int SMEM_TOTAL = SM_INVY + BN * 4;         // 111616

__device__ __forceinline__ uint32_t f2tf(float f) {
    uint32_t u;
    asm("cvt.rna.tf32.f32 %0, %1;" : "=r"(u) : "f"(f));
    return u;
}
__device__ __forceinline__ uint32_t ldcv(const uint32_t* p) {
    return f2tf(__uint_as_float(*p));
}
__device__ __forceinline__ void mma_tf32(float c[4], const uint32_t a[4],
                                         uint32_t b0, uint32_t b1) {
    asm volatile(
        "mma.sync.aligned.m16n8k8.row.col.f32.tf32.tf32.f32 "
        "{%0,%1,%2,%3}, {%4,%5,%6,%7}, {%8,%9}, {%0,%1,%2,%3};"
        : "+f"(c[0]), "+f"(c[1]), "+f"(c[2]), "+f"(c[3])
        : "r"(a[0]), "r"(a[1]), "r"(a[2]), "r"(a[3]), "r"(b0), "r"(b1));
}
__device__ __forceinline__ float dot4(float4 v) {
    return v.x * v.x + v.y * v.y + v.z * v.z + v.w * v.w;
}
__device__ __forceinline__ void cp16(uint32_t smem, const void* g) {
    asm volatile("cp.async.cg.shared.global [%0], [%1], 16;" :: "r"(smem), "l"(g));
}
__device__ __forceinline__ void cp_commit() {
    asm volatile("cp.async.commit_group;" ::: "memory");
}
template <int N>
__device__ __forceinline__ void cp_wait() {
    asm volatile("cp.async.wait_group %0;" :: "n"(N) : "memory");
}

__global__ __launch_bounds__(256, 2)
void cos_gemm_pipe(const float* __restrict__ X,
                   const float* __restrict__ Y,
                   float* __restrict__ out) {
    extern __shared__ char smraw[];
    uint32_t* sbase = reinterpret_cast<uint32_t*>(smraw);
    float* sinvx = reinterpret_cast<float*>(smraw + SM_INVX);
    float* sinvy = reinterpret_cast<float*>(smraw + SM_INVY);
    const uint32_t smadr = (uint32_t)__cvta_generic_to_shared(smraw);

    const int tid  = threadIdx.x;
    const int b    = blockIdx.z;
    const int mcta = blockIdx.x * BM;
    const int ncta = blockIdx.y * BN;

    const float* A  = X + (size_t)b * Tn * Dn + (size_t)mcta * Dn;
    const float* Bp = Y + (size_t)b * Sn * Dn + (size_t)ncta * Dn;

    // -------- producer mapping: 8 x 16B cp.async per thread per tile ------
    const int q  = tid & 7;
    const int r0 = tid >> 3;
    const float* gA = A  + (size_t)r0 * Dn + q * 4;
    const float* gB = Bp + (size_t)r0 * Dn + q * 4;
    int soff[4];                           // u32 index within a tile buffer
    #pragma unroll
    for (int p = 0; p < 4; ++p)
        soff[p] = (r0 + 32 * p) * SSTR + q * 4;

    auto FILL = [&](int kt, int stg) {
        const int ko = kt * BK;
        const uint32_t sa = smadr + stg * STAGE_U32 * 4;
        const uint32_t sb = sa + AU32 * 4;
        #pragma unroll
        for (int p = 0; p < 4; ++p) {
            cp16(sa + soff[p] * 4, gA + (size_t)(32 * p) * Dn + ko);
            cp16(sb + soff[p] * 4, gB + (size_t)(32 * p) * Dn + ko);
        }
        cp_commit();
    };

    // -------- compute mapping: 8 warps 4x2, warp tile 32x64 ---------------
    const int wid  = tid >> 5;
    const int lane = tid & 31;
    const int wm   = wid >> 1;            // 0..3 (M dir, 32 rows)
    const int wn   = wid & 1;             // 0..1 (N dir, 64 cols)
    const int gid  = lane >> 2;           // 0..7
    const int tig  = lane & 3;            // 0..3

    float acc[2][8][4];
    #pragma unroll
    for (int i = 0; i < 2; ++i)
        #pragma unroll
        for (int j = 0; j < 8; ++j)
            #pragma unroll
            for (int p = 0; p < 4; ++p)
                acc[i][j][p] = 0.0f;

    float nx[4] = {0, 0, 0, 0}, ny[4] = {0, 0, 0, 0};

    FILL(0, 0);
    FILL(1, 1);

    int stg = 0;
    #pragma unroll 1
    for (int kt = 0; kt < NT; ++kt) {
        if (kt < NT - 1) cp_wait<1>(); else cp_wait<0>();
        __syncthreads();                 // stage kt ready; stage (kt+2)%3 free

        if (kt + 2 < NT) {
            int ns = stg + 2; if (ns >= STAGES) ns -= STAGES;
            FILL(kt + 2, ns);
        }

        const uint32_t* Ab = sbase + stg * STAGE_U32;
        const uint32_t* Bb = Ab + AU32;

        // ---- norms: read back exactly the float4s this thread delivered --
        #pragma unroll
        for (int p = 0; p < 4; ++p) {
            nx[p] += dot4(*reinterpret_cast<const float4*>(Ab + soff[p]));
            ny[p] += dot4(*reinterpret_cast<const float4*>(Bb + soff[p]));
        }

        // ---- software-pipelined fragment loads + mma ----
        uint32_t a[2][2][4];             // [set][i][frag]
        uint32_t bf[2][4][2];            // [half-set][j][frag]

        // fragment loaders (cvt.rna fused)
        auto LDA = [&](uint32_t dst[2][4], int s) {
            const int kb = s * 8;
            #pragma unroll
            for (int i = 0; i < 2; ++i) {
                const int r = wm * 32 + i * 16 + gid;
                dst[i][0] = ldcv(Ab + r * SSTR + kb + tig);
                dst[i][1] = ldcv(Ab + (r + 8) * SSTR + kb + tig);
                dst[i][2] = ldcv(Ab + r * SSTR + kb + tig + 4);
                dst[i][3] = ldcv(Ab + (r + 8) * SSTR + kb + tig + 4);
            }
        };
        auto LDB = [&](uint32_t dst[4][2], int s, int h) {
            const int kb = s * 8;
            #pragma unroll
            for (int j = 0; j < 4; ++j) {
                const int n0 = wn * 64 + (4 * h + j) * 8 + gid;
                dst[j][0] = ldcv(Bb + n0 * SSTR + kb + tig);
                dst[j][1] = ldcv(Bb + n0 * SSTR + kb + tig + 4);
            }
        };
        auto MMAB = [&](uint32_t as[2][4], uint32_t bs[4][2], int h) {
            #pragma unroll
            for (int j = 0; j < 4; ++j) {
                mma_tf32(acc[0][4 * h + j], as[0], bs[j][0], bs[j][1]);
                mma_tf32(acc[1][4 * h + j], as[1], bs[j][0], bs[j][1]);
            }
        };

        LDA(a[0], 0);
        LDB(bf[0], 0, 0);
        #pragma unroll
        for (int s = 0; s < 4; ++s) {
            LDB(bf[1], s, 1);            // half1 of s, lands under half0 mmas
            MMAB(a[s & 1], bf[0], 0);
            if (s < 3) {
                LDA(a[(s + 1) & 1], s + 1);   // next step, under half1 mmas
                LDB(bf[0], s + 1, 0);
            }
            MMAB(a[s & 1], bf[1], 1);
        }

        ++stg; if (stg >= STAGES) stg -= STAGES;
        __syncthreads();                 // done reading stage before refill wraps
    }

    // -------- finish norms: reduce across the 8 k-quad threads per row ----
    #pragma unroll
    for (int p = 0; p < 4; ++p) {
        float s = nx[p];
        s += __shfl_xor_sync(0xffffffffu, s, 1);
        s += __shfl_xor_sync(0xffffffffu, s, 2);
        s += __shfl_xor_sync(0xffffffffu, s, 4);
        float t = ny[p];
        t += __shfl_xor_sync(0xffffffffu, t, 1);
        t += __shfl_xor_sync(0xffffffffu, t, 2);
        t += __shfl_xor_sync(0xffffffffu, t, 4);
        if (q == 0) {
            sinvx[r0 + 32 * p] = 1.0f / fmaxf(sqrtf(s), EPS_F);
            sinvy[r0 + 32 * p] = 1.0f / fmaxf(sqrtf(t), EPS_F);
        }
    }
    __syncthreads();

    // -------- epilogue: scale by inverse norms, float2 stores --------
    float* C = out + (size_t)b * Tn * Sn + (size_t)mcta * Sn + ncta;

    #pragma unroll
    for (int i = 0; i < 2; ++i) {
        const int rA = wm * 32 + i * 16 + gid;
        const float sx0 = sinvx[rA];
        const float sx1 = sinvx[rA + 8];
        #pragma unroll
        for (int j = 0; j < 8; ++j) {
            const int c0 = wn * 64 + j * 8 + tig * 2;
            const float sy0 = sinvy[c0];
            const float sy1 = sinvy[c0 + 1];
            float2 w;
            w.x = acc[i][j][0] * sx0 * sy0;
            w.y = acc[i][j][1] * sx0 * sy1;
            *reinterpret_cast<float2*>(&C[(size_t)rA * Sn + c0]) = w;
            w.x = acc[i][j][2] * sx1 * sy0;
            w.y = acc[i][j][3] * sx1 * sy1;
            *reinterpret_cast<float2*>(&C[(size_t)(rA + 8) * Sn + c0]) = w;
        }
    }
}

extern "C" void kernel_launch(void* const* d_in, const int* in_sizes, int n_in,
                              void* d_out, int out_size) {
    const float* xs  = (const float*)d_in[0];   // (8, 4096, 512)
    const float* spk = (const float*)d_in[1];   // (8, 256, 512)
    float* out = (float*)d_out;                 // (8, 4096, 256)

    static bool attr_set = false;
    if (!attr_set) {
        cudaFuncSetAttribute(cos_gemm_pipe,
                             cudaFuncAttributeMaxDynamicSharedMemorySize,
                             SMEM_TOTAL);
        attr_set = true;
    }

    dim3 grid(Tn / BM, Sn / BN, Bn);            // (32, 2, 8) = 512 CTAs
    cos_gemm_pipe<<<grid, 256, SMEM_TOTAL>>>(xs, spk, out);
}

// round 13
// speedup vs baseline: 1.4600x; 1.2213x over previous
#include <cuda_runtime.h>
#include <cuda_fp16.h>
#include <cstdint>

// Problem shape (fixed per reference setup_inputs)
constexpr int Bn = 8;     // batch
constexpr int Tn = 4096;  // xs rows (M)
constexpr int Sn = 256;   // spk rows (N)
constexpr int Dn = 512;   // feature (K)

#define EPS_F 1e-8f

// ---------------------------------------------------------------------------
// Fused kernel: per-batch NT GEMM via FP16 m16n8k16 mma.sync (fp32 accum)
// + in-register fp32 row norms.  C = (X/||X||) (Y/||Y||)^T.
// CTA tile 128x128, BK=32 floats (16 half2/row), 256 threads (8 warps, 4x2),
// warp tile 32x64.  smem half2 stride 20 -> conflict-free fragment LDS.
// Register producer (LDG->cvt->STS.128), norms fused, 1 sync per k-tile.
// ---------------------------------------------------------------------------
constexpr int BM = 128, BN = 128, BK = 32;   // BK in floats
constexpr int SSTR = 20;                 // smem row stride in half2 (16 data + 4 pad)
constexpr int NT = Dn / BK;              // 16 k-tiles
constexpr int TILE_H2 = BM * SSTR;       // 2560 half2 per tile buffer

__device__ __forceinline__ uint32_t pack2(float lo, float hi) {
    __half2 h = __floats2half2_rn(lo, hi);
    return *reinterpret_cast<uint32_t*>(&h);
}

__device__ __forceinline__ void mma_f16(float c[4], const uint32_t a[4],
                                        uint32_t b0, uint32_t b1) {
    asm volatile(
        "mma.sync.aligned.m16n8k16.row.col.f32.f16.f16.f32 "
        "{%0,%1,%2,%3}, {%4,%5,%6,%7}, {%8,%9}, {%0,%1,%2,%3};"
        : "+f"(c[0]), "+f"(c[1]), "+f"(c[2]), "+f"(c[3])
        : "r"(a[0]), "r"(a[1]), "r"(a[2]), "r"(a[3]), "r"(b0), "r"(b1));
}

__device__ __forceinline__ float dot4(float4 v) {
    return v.x * v.x + v.y * v.y + v.z * v.z + v.w * v.w;
}

__global__ __launch_bounds__(256, 2)
void cos_gemm_f16(const float* __restrict__ X,
                  const float* __restrict__ Y,
                  float* __restrict__ out) {
    __shared__ uint32_t As[2][TILE_H2];     // half2-packed, 10240 B per buf
    __shared__ uint32_t Bs[2][TILE_H2];
    __shared__ float sinvx[BM];
    __shared__ float sinvy[BN];

    const int tid  = threadIdx.x;
    const int b    = blockIdx.z;
    const int mcta = blockIdx.x * BM;
    const int ncta = blockIdx.y * BN;

    const float* A  = X + (size_t)b * Tn * Dn + (size_t)mcta * Dn;
    const float* Bp = Y + (size_t)b * Sn * Dn + (size_t)ncta * Dn;

    // -------- producer mapping: thread -> (row r, k-octet q) --------------
    // Each thread: 8 consecutive floats (2 float4) of rows {r, r+64} for A
    // and B -> 4 half2 each = one STS.128 per row-half.
    const int q = tid & 3;               // k-octet 0..3 (8 floats)
    const int r = tid >> 2;              // row 0..63
    const float* gA = A  + (size_t)r * Dn + q * 8;
    const float* gB = Bp + (size_t)r * Dn + q * 8;
    const int sof0 = r * SSTR + q * 4;           // half2 index, row r
    const int sof1 = (r + 64) * SSTR + q * 4;    // row r+64

    // -------- compute mapping: 8 warps 4x2, warp tile 32x64 ---------------
    const int wid  = tid >> 5;
    const int lane = tid & 31;
    const int wm   = wid >> 1;           // 0..3 (M dir, 32 rows)
    const int wn   = wid & 1;            // 0..1 (N dir, 64 cols)
    const int gid  = lane >> 2;          // 0..7
    const int tig  = lane & 3;           // 0..3

    float acc[2][8][4];
    #pragma unroll
    for (int i = 0; i < 2; ++i)
        #pragma unroll
        for (int j = 0; j < 8; ++j)
            #pragma unroll
            for (int p = 0; p < 4; ++p)
                acc[i][j][p] = 0.0f;

    // norm partials: rows (r, r+64) of A and B, octet-q slice (exact fp32)
    float nx0 = 0.0f, nx1 = 0.0f, ny0 = 0.0f, ny1 = 0.0f;

    // staging: [0]=A row r, [1]=A row r+64, [2]=B row r, [3]=B row r+64
    float4 st[4][2];

    auto LDG = [&](int kt) {
        const int ko = kt * BK;
        st[0][0] = *reinterpret_cast<const float4*>(gA + ko);
        st[0][1] = *reinterpret_cast<const float4*>(gA + ko + 4);
        st[1][0] = *reinterpret_cast<const float4*>(gA + (size_t)64 * Dn + ko);
        st[1][1] = *reinterpret_cast<const float4*>(gA + (size_t)64 * Dn + ko + 4);
        st[2][0] = *reinterpret_cast<const float4*>(gB + ko);
        st[2][1] = *reinterpret_cast<const float4*>(gB + ko + 4);
        st[3][0] = *reinterpret_cast<const float4*>(gB + (size_t)64 * Dn + ko);
        st[3][1] = *reinterpret_cast<const float4*>(gB + (size_t)64 * Dn + ko + 4);
    };
    auto STS1 = [&](uint32_t* dst, const float4& f0, const float4& f1) {
        uint4 u;
        u.x = pack2(f0.x, f0.y);
        u.y = pack2(f0.z, f0.w);
        u.z = pack2(f1.x, f1.y);
        u.w = pack2(f1.z, f1.w);
        *reinterpret_cast<uint4*>(dst) = u;
    };
    auto STSN = [&](int buf) {
        uint32_t* Ad = As[buf];
        uint32_t* Bd = Bs[buf];
        nx0 += dot4(st[0][0]) + dot4(st[0][1]);
        STS1(Ad + sof0, st[0][0], st[0][1]);
        nx1 += dot4(st[1][0]) + dot4(st[1][1]);
        STS1(Ad + sof1, st[1][0], st[1][1]);
        ny0 += dot4(st[2][0]) + dot4(st[2][1]);
        STS1(Bd + sof0, st[2][0], st[2][1]);
        ny1 += dot4(st[3][0]) + dot4(st[3][1]);
        STS1(Bd + sof1, st[3][0], st[3][1]);
    };

    LDG(0);
    STSN(0);
    __syncthreads();

    #pragma unroll 1
    for (int kt = 0; kt < NT; ++kt) {
        const int cur = kt & 1;
        const bool more = (kt + 1 < NT);

        // prefetch next tile to registers; drains under the mma block
        if (more) LDG(kt + 1);

        const uint32_t* __restrict__ Ab = As[cur];
        const uint32_t* __restrict__ Bb = Bs[cur];

        #pragma unroll
        for (int s = 0; s < 2; ++s) {    // two k=16 steps per tile
            const int kb = s * 8;        // half2 index base
            uint32_t a[2][4];
            #pragma unroll
            for (int i = 0; i < 2; ++i) {
                const int rr = wm * 32 + i * 16 + gid;
                a[i][0] = Ab[rr * SSTR + kb + tig];
                a[i][1] = Ab[(rr + 8) * SSTR + kb + tig];
                a[i][2] = Ab[rr * SSTR + kb + tig + 4];
                a[i][3] = Ab[(rr + 8) * SSTR + kb + tig + 4];
            }
            #pragma unroll
            for (int j = 0; j < 8; ++j) {
                const int n0 = wn * 64 + j * 8 + gid;
                uint32_t b0 = Bb[n0 * SSTR + kb + tig];
                uint32_t b1 = Bb[n0 * SSTR + kb + tig + 4];
                mma_f16(acc[0][j], a[0], b0, b1);
                mma_f16(acc[1][j], a[1], b0, b1);
            }
        }

        // store into the buffer all warps stopped reading before prev sync
        if (more) STSN((kt + 1) & 1);
        __syncthreads();
    }

    // -------- finish norms: reduce across 4 octet-threads per row ---------
    // threads tid = 4*r + q are contiguous lanes within one warp.
    nx0 += __shfl_xor_sync(0xffffffffu, nx0, 1);
    nx0 += __shfl_xor_sync(0xffffffffu, nx0, 2);
    nx1 += __shfl_xor_sync(0xffffffffu, nx1, 1);
    nx1 += __shfl_xor_sync(0xffffffffu, nx1, 2);
    ny0 += __shfl_xor_sync(0xffffffffu, ny0, 1);
    ny0 += __shfl_xor_sync(0xffffffffu, ny0, 2);
    ny1 += __shfl_xor_sync(0xffffffffu, ny1, 1);
    ny1 += __shfl_xor_sync(0xffffffffu, ny1, 2);
    if (q == 0) {
        sinvx[r]      = 1.0f / fmaxf(sqrtf(nx0), EPS_F);
        sinvx[r + 64] = 1.0f / fmaxf(sqrtf(nx1), EPS_F);
        sinvy[r]      = 1.0f / fmaxf(sqrtf(ny0), EPS_F);
        sinvy[r + 64] = 1.0f / fmaxf(sqrtf(ny1), EPS_F);
    }
    __syncthreads();

    // -------- epilogue: scale by inverse norms, float2 stores --------
    float* C = out + (size_t)b * Tn * Sn + (size_t)mcta * Sn + ncta;

    #pragma unroll
    for (int i = 0; i < 2; ++i) {
        const int rA = wm * 32 + i * 16 + gid;
        const float sx0 = sinvx[rA];
        const float sx1 = sinvx[rA + 8];
        #pragma unroll
        for (int j = 0; j < 8; ++j) {
            const int c0 = wn * 64 + j * 8 + tig * 2;
            const float sy0 = sinvy[c0];
            const float sy1 = sinvy[c0 + 1];
            float2 w;
            w.x = acc[i][j][0] * sx0 * sy0;
            w.y = acc[i][j][1] * sx0 * sy1;
            *reinterpret_cast<float2*>(&C[(size_t)rA * Sn + c0]) = w;
            w.x = acc[i][j][2] * sx1 * sy0;
            w.y = acc[i][j][3] * sx1 * sy1;
            *reinterpret_cast<float2*>(&C[(size_t)(rA + 8) * Sn + c0]) = w;
        }
    }
}

extern "C" void kernel_launch(void* const* d_in, const int* in_sizes, int n_in,
                              void* d_out, int out_size) {
    const float* xs  = (const float*)d_in[0];   // (8, 4096, 512)
    const float* spk = (const float*)d_in[1];   // (8, 256, 512)
    float* out = (float*)d_out;                 // (8, 4096, 256)

    dim3 grid(Tn / BM, Sn / BN, Bn);            // (32, 2, 8) = 512 CTAs
    cos_gemm_f16<<<grid, 256>>>(xs, spk, out);
}

// round 14
// speedup vs baseline: 1.7089x; 1.1704x over previous
#include <cuda_runtime.h>
#include <cuda_fp16.h>
#include <cstdint>

// Problem shape (fixed per reference setup_inputs)
constexpr int Bn = 8;     // batch
constexpr int Tn = 4096;  // xs rows (M)
constexpr int Sn = 256;   // spk rows (N)
constexpr int Dn = 512;   // feature (K)

#define EPS_F 1e-8f

constexpr int NX = Bn * Tn;   // 32768 x-rows
constexpr int NY = Bn * Sn;   // 2048  y-rows

// __device__ scratch (static globals are the sanctioned no-alloc path)
__device__ __half g_x16[(size_t)NX * Dn];   // 33.5 MB fp16 copy of X
__device__ __half g_y16[(size_t)NY * Dn];   // 2 MB fp16 copy of Y
__device__ float  g_invnx[NX];
__device__ float  g_invny[NY];

__device__ __forceinline__ uint32_t pack2(float lo, float hi) {
    __half2 h = __floats2half2_rn(lo, hi);
    return *reinterpret_cast<uint32_t*>(&h);
}
__device__ __forceinline__ float dot4(float4 v) {
    return v.x * v.x + v.y * v.y + v.z * v.z + v.w * v.w;
}

// ---------------------------------------------------------------------------
// Kernel 1: prep — fp32 -> fp16 conversion + exact fp32 inverse row norms.
// One warp per row (512 floats): 4 float4 per lane, coalesced uint2 writes.
// ---------------------------------------------------------------------------
__global__ void cos_prep(const float* __restrict__ x,
                         const float* __restrict__ y) {
    const int gw   = (blockIdx.x * blockDim.x + threadIdx.x) >> 5;
    const int lane = threadIdx.x & 31;

    const float* src;
    __half* dst;
    float* ninv;
    if (gw < NX) {
        src  = x + (size_t)gw * Dn;
        dst  = g_x16 + (size_t)gw * Dn;
        ninv = &g_invnx[gw];
    } else {
        const int r = gw - NX;
        if (r >= NY) return;
        src  = y + (size_t)r * Dn;
        dst  = g_y16 + (size_t)r * Dn;
        ninv = &g_invny[r];
    }

    const float4* v4 = reinterpret_cast<const float4*>(src);
    uint2* d2 = reinterpret_cast<uint2*>(dst);
    float s = 0.0f;
    #pragma unroll
    for (int i = 0; i < Dn / (4 * 32); ++i) {   // 4 float4 per lane
        float4 f = v4[lane + 32 * i];
        s += dot4(f);
        uint2 u;
        u.x = pack2(f.x, f.y);
        u.y = pack2(f.z, f.w);
        d2[lane + 32 * i] = u;
    }
    #pragma unroll
    for (int o = 16; o > 0; o >>= 1)
        s += __shfl_xor_sync(0xffffffffu, s, o);
    if (lane == 0)
        *ninv = 1.0f / fmaxf(sqrtf(s), EPS_F);
}

// ---------------------------------------------------------------------------
// Kernel 2: lean fp16 GEMM, m16n8k16 mma.sync, fp32 accum.
// CTA tile 128x128, BK=64 halves (128B rows), 256 threads (8 warps 4x2),
// warp tile 32x64. cp.async.cg 3-stage pipeline of fp16; stride-36 u32 rows
// -> conflict-free fragment LDS. Epilogue scales by precomputed inv norms.
// ---------------------------------------------------------------------------
constexpr int BM = 128, BN = 128;
constexpr int BKH = 64;                   // k-chunk in halves (128 B)
constexpr int NT  = Dn / BKH;             // 8 k-tiles
constexpr int SSTR = 36;                  // row stride in u32 (32 data + 4 pad)
constexpr int AU32 = BM * SSTR;           // 4608 u32 per A (or B) tile
constexpr int STAGES = 3;
constexpr int STAGE_U32 = 2 * AU32;       // A then B
constexpr int SMEM_TOTAL = STAGES * STAGE_U32 * 4;   // 110592 B

__device__ __forceinline__ void mma_f16(float c[4], const uint32_t a[4],
                                        uint32_t b0, uint32_t b1) {
    asm volatile(
        "mma.sync.aligned.m16n8k16.row.col.f32.f16.f16.f32 "
        "{%0,%1,%2,%3}, {%4,%5,%6,%7}, {%8,%9}, {%0,%1,%2,%3};"
        : "+f"(c[0]), "+f"(c[1]), "+f"(c[2]), "+f"(c[3])
        : "r"(a[0]), "r"(a[1]), "r"(a[2]), "r"(a[3]), "r"(b0), "r"(b1));
}
__device__ __forceinline__ void cp16(uint32_t smem, const void* g) {
    asm volatile("cp.async.cg.shared.global [%0], [%1], 16;" :: "r"(smem), "l"(g));
}
__device__ __forceinline__ void cp_commit() {
    asm volatile("cp.async.commit_group;" ::: "memory");
}
template <int N>
__device__ __forceinline__ void cp_wait() {
    asm volatile("cp.async.wait_group %0;" :: "n"(N) : "memory");
}

__global__ __launch_bounds__(256, 2)
void cos_gemm2(float* __restrict__ out) {
    extern __shared__ char smraw[];
    uint32_t* sbase = reinterpret_cast<uint32_t*>(smraw);
    const uint32_t smadr = (uint32_t)__cvta_generic_to_shared(smraw);

    const int tid  = threadIdx.x;
    const int b    = blockIdx.z;
    const int mcta = blockIdx.x * BM;
    const int ncta = blockIdx.y * BN;

    const __half* A  = g_x16 + (size_t)(b * Tn + mcta) * Dn;
    const __half* Bp = g_y16 + (size_t)(b * Sn + ncta) * Dn;

    // -------- cp.async mapping: 8 x 16B per thread per tile (A:4, B:4) ----
    // thread -> (chunk q = tid&7 within 128B row, base row r0 = tid>>3),
    // rows r0 + 32p, p = 0..3.
    const int q  = tid & 7;
    const int r0 = tid >> 3;
    const __half* gA = A  + (size_t)r0 * Dn + q * 8;
    const __half* gB = Bp + (size_t)r0 * Dn + q * 8;
    int soff[4];                           // u32 index within a tile buffer
    #pragma unroll
    for (int p = 0; p < 4; ++p)
        soff[p] = (r0 + 32 * p) * SSTR + q * 4;

    auto FILL = [&](int kt, int stg) {
        const int ko = kt * BKH;
        const uint32_t sa = smadr + stg * STAGE_U32 * 4;
        const uint32_t sb = sa + AU32 * 4;
        #pragma unroll
        for (int p = 0; p < 4; ++p) {
            cp16(sa + soff[p] * 4, gA + (size_t)(32 * p) * Dn + ko);
            cp16(sb + soff[p] * 4, gB + (size_t)(32 * p) * Dn + ko);
        }
        cp_commit();
    };

    // -------- compute mapping: 8 warps 4x2, warp tile 32x64 ---------------
    const int wid  = tid >> 5;
    const int lane = tid & 31;
    const int wm   = wid >> 1;            // 0..3 (M dir, 32 rows)
    const int wn   = wid & 1;             // 0..1 (N dir, 64 cols)
    const int gid  = lane >> 2;           // 0..7
    const int tig  = lane & 3;            // 0..3

    float acc[2][8][4];
    #pragma unroll
    for (int i = 0; i < 2; ++i)
        #pragma unroll
        for (int j = 0; j < 8; ++j)
            #pragma unroll
            for (int p = 0; p < 4; ++p)
                acc[i][j][p] = 0.0f;

    FILL(0, 0);
    FILL(1, 1);

    int stg = 0;
    #pragma unroll 1
    for (int kt = 0; kt < NT; ++kt) {
        if (kt < NT - 1) cp_wait<1>(); else cp_wait<0>();
        __syncthreads();                 // stage kt ready; oldest stage free

        if (kt + 2 < NT) {
            int ns = stg + 2; if (ns >= STAGES) ns -= STAGES;
            FILL(kt + 2, ns);
        }

        const uint32_t* __restrict__ Ab = sbase + stg * STAGE_U32;
        const uint32_t* __restrict__ Bb = Ab + AU32;

        #pragma unroll
        for (int s = 0; s < 4; ++s) {    // four k=16 steps per tile
            const int kb = s * 8;        // u32 base within row
            uint32_t a[2][4];
            #pragma unroll
            for (int i = 0; i < 2; ++i) {
                const int rr = wm * 32 + i * 16 + gid;
                a[i][0] = Ab[rr * SSTR + kb + tig];
                a[i][1] = Ab[(rr + 8) * SSTR + kb + tig];
                a[i][2] = Ab[rr * SSTR + kb + tig + 4];
                a[i][3] = Ab[(rr + 8) * SSTR + kb + tig + 4];
            }
            #pragma unroll
            for (int j = 0; j < 8; ++j) {
                const int n0 = wn * 64 + j * 8 + gid;
                uint32_t b0 = Bb[n0 * SSTR + kb + tig];
                uint32_t b1 = Bb[n0 * SSTR + kb + tig + 4];
                mma_f16(acc[0][j], a[0], b0, b1);
                mma_f16(acc[1][j], a[1], b0, b1);
            }
        }

        ++stg; if (stg >= STAGES) stg -= STAGES;
        __syncthreads();                 // done reading stage before refill
    }

    // -------- epilogue: scale by precomputed inverse norms ----------------
    const float* invx = g_invnx + b * Tn + mcta;
    const float* invy = g_invny + b * Sn + ncta;
    float* C = out + (size_t)b * Tn * Sn + (size_t)mcta * Sn + ncta;

    #pragma unroll
    for (int i = 0; i < 2; ++i) {
        const int rA = wm * 32 + i * 16 + gid;
        const float sx0 = invx[rA];
        const float sx1 = invx[rA + 8];
        #pragma unroll
        for (int j = 0; j < 8; ++j) {
            const int c0 = wn * 64 + j * 8 + tig * 2;
            const float sy0 = invy[c0];
            const float sy1 = invy[c0 + 1];
            float2 w;
            w.x = acc[i][j][0] * sx0 * sy0;
            w.y = acc[i][j][1] * sx0 * sy1;
            *reinterpret_cast<float2*>(&C[(size_t)rA * Sn + c0]) = w;
            w.x = acc[i][j][2] * sx1 * sy0;
            w.y = acc[i][j][3] * sx1 * sy1;
            *reinterpret_cast<float2*>(&C[(size_t)(rA + 8) * Sn + c0]) = w;
        }
    }
}

extern "C" void kernel_launch(void* const* d_in, const int* in_sizes, int n_in,
                              void* d_out, int out_size) {
    const float* xs  = (const float*)d_in[0];   // (8, 4096, 512)
    const float* spk = (const float*)d_in[1];   // (8, 256, 512)
    float* out = (float*)d_out;                 // (8, 4096, 256)

    static bool attr_set = false;
    if (!attr_set) {
        cudaFuncSetAttribute(cos_gemm2,
                             cudaFuncAttributeMaxDynamicSharedMemorySize,
                             SMEM_TOTAL);
        attr_set = true;
    }

    {   // prep: 34816 row-warps, 8 warps per 256-thread block
        int blocks = (NX + NY + 7) / 8;
        cos_prep<<<blocks, 256>>>(xs, spk);
    }
    {
        dim3 grid(Tn / BM, Sn / BN, Bn);        // (32, 2, 8) = 512 CTAs
        cos_gemm2<<<grid, 256, SMEM_TOTAL>>>(out);
    }
}

// round 15
// speedup vs baseline: 1.7203x; 1.0067x over previous
#include <cuda_runtime.h>
#include <cuda_fp16.h>
#include <cstdint>

// Problem shape (fixed per reference setup_inputs)
constexpr int Bn = 8;     // batch
constexpr int Tn = 4096;  // xs rows (M)
constexpr int Sn = 256;   // spk rows (N)
constexpr int Dn = 512;   // feature (K)

#define EPS_F 1e-8f

constexpr int NX = Bn * Tn;   // 32768 x-rows
constexpr int NY = Bn * Sn;   // 2048  y-rows

// __device__ scratch (static globals are the sanctioned no-alloc path)
__device__ __half g_x16[(size_t)NX * Dn];   // 33.5 MB fp16 copy of X
__device__ __half g_y16[(size_t)NY * Dn];   // 2 MB fp16 copy of Y
__device__ float  g_invnx[NX];
__device__ float  g_invny[NY];

__device__ __forceinline__ uint32_t pack2(float lo, float hi) {
    __half2 h = __floats2half2_rn(lo, hi);
    return *reinterpret_cast<uint32_t*>(&h);
}
__device__ __forceinline__ float dot4(float4 v) {
    return v.x * v.x + v.y * v.y + v.z * v.z + v.w * v.w;
}

// ---------------------------------------------------------------------------
// Kernel 1: prep — fp32 -> fp16 conversion + exact fp32 inverse row norms.
// One warp per row (512 floats): 4 float4 per lane, coalesced uint2 writes.
// (Measured ~6 TB/s effective — bandwidth-optimal; unchanged.)
// ---------------------------------------------------------------------------
__global__ void cos_prep(const float* __restrict__ x,
                         const float* __restrict__ y) {
    const int gw   = (blockIdx.x * blockDim.x + threadIdx.x) >> 5;
    const int lane = threadIdx.x & 31;

    const float* src;
    __half* dst;
    float* ninv;
    if (gw < NX) {
        src  = x + (size_t)gw * Dn;
        dst  = g_x16 + (size_t)gw * Dn;
        ninv = &g_invnx[gw];
    } else {
        const int r = gw - NX;
        if (r >= NY) return;
        src  = y + (size_t)r * Dn;
        dst  = g_y16 + (size_t)r * Dn;
        ninv = &g_invny[r];
    }

    const float4* v4 = reinterpret_cast<const float4*>(src);
    uint2* d2 = reinterpret_cast<uint2*>(dst);
    float s = 0.0f;
    #pragma unroll
    for (int i = 0; i < Dn / (4 * 32); ++i) {   // 4 float4 per lane
        float4 f = v4[lane + 32 * i];
        s += dot4(f);
        uint2 u;
        u.x = pack2(f.x, f.y);
        u.y = pack2(f.z, f.w);
        d2[lane + 32 * i] = u;
    }
    #pragma unroll
    for (int o = 16; o > 0; o >>= 1)
        s += __shfl_xor_sync(0xffffffffu, s, o);
    if (lane == 0)
        *ninv = 1.0f / fmaxf(sqrtf(s), EPS_F);
}

// ---------------------------------------------------------------------------
// Kernel 2: lean fp16 GEMM, m16n8k16 mma.sync, fp32 accum, LDSM fragments.
// CTA tile 128x128, BK=64 halves (128B rows), 256 threads (8 warps 4x2),
// warp tile 32x64. cp.async.cg 3-stage pipeline; stride-36 u32 rows ->
// conflict-free ldmatrix phases. ONE __syncthreads per k-tile.
// ---------------------------------------------------------------------------
constexpr int BM = 128, BN = 128;
constexpr int BKH = 64;                   // k-chunk in halves (128 B)
constexpr int NT  = Dn / BKH;             // 8 k-tiles
constexpr int SSTR = 36;                  // row stride in u32 (32 data + 4 pad)
constexpr int AU32 = BM * SSTR;           // 4608 u32 per A (or B) tile
constexpr int STAGES = 3;
constexpr int STAGE_U32 = 2 * AU32;       // A then B
constexpr int SMEM_TOTAL = STAGES * STAGE_U32 * 4;   // 110592 B

__device__ __forceinline__ void mma_f16(float c[4], const uint32_t a[4],
                                        uint32_t b0, uint32_t b1) {
    asm volatile(
        "mma.sync.aligned.m16n8k16.row.col.f32.f16.f16.f32 "
        "{%0,%1,%2,%3}, {%4,%5,%6,%7}, {%8,%9}, {%0,%1,%2,%3};"
        : "+f"(c[0]), "+f"(c[1]), "+f"(c[2]), "+f"(c[3])
        : "r"(a[0]), "r"(a[1]), "r"(a[2]), "r"(a[3]), "r"(b0), "r"(b1));
}
__device__ __forceinline__ void ldsm_x4(uint32_t r[4], uint32_t addr) {
    asm volatile(
        "ldmatrix.sync.aligned.m8n8.x4.shared.b16 {%0,%1,%2,%3}, [%4];"
        : "=r"(r[0]), "=r"(r[1]), "=r"(r[2]), "=r"(r[3]) : "r"(addr));
}
__device__ __forceinline__ void cp16(uint32_t smem, const void* g) {
    asm volatile("cp.async.cg.shared.global [%0], [%1], 16;" :: "r"(smem), "l"(g));
}
__device__ __forceinline__ void cp_commit() {
    asm volatile("cp.async.commit_group;" ::: "memory");
}
template <int N>
__device__ __forceinline__ void cp_wait() {
    asm volatile("cp.async.wait_group %0;" :: "n"(N) : "memory");
}

__global__ __launch_bounds__(256, 2)
void cos_gemm3(float* __restrict__ out) {
    extern __shared__ char smraw[];
    const uint32_t smadr = (uint32_t)__cvta_generic_to_shared(smraw);

    const int tid  = threadIdx.x;
    const int b    = blockIdx.z;
    const int mcta = blockIdx.x * BM;
    const int ncta = blockIdx.y * BN;

    const __half* A  = g_x16 + (size_t)(b * Tn + mcta) * Dn;
    const __half* Bp = g_y16 + (size_t)(b * Sn + ncta) * Dn;

    // -------- cp.async mapping: 8 x 16B per thread per tile (A:4, B:4) ----
    const int q  = tid & 7;
    const int r0 = tid >> 3;
    const __half* gA = A  + (size_t)r0 * Dn + q * 8;
    const __half* gB = Bp + (size_t)r0 * Dn + q * 8;
    int soff[4];                           // u32 index within a tile buffer
    #pragma unroll
    for (int p = 0; p < 4; ++p)
        soff[p] = (r0 + 32 * p) * SSTR + q * 4;

    auto FILL = [&](int kt, int stg) {
        const int ko = kt * BKH;
        const uint32_t sa = smadr + stg * STAGE_U32 * 4;
        const uint32_t sb = sa + AU32 * 4;
        #pragma unroll
        for (int p = 0; p < 4; ++p) {
            cp16(sa + soff[p] * 4, gA + (size_t)(32 * p) * Dn + ko);
            cp16(sb + soff[p] * 4, gB + (size_t)(32 * p) * Dn + ko);
        }
        cp_commit();
    };

    // -------- compute mapping: 8 warps 4x2, warp tile 32x64 ---------------
    const int wid  = tid >> 5;
    const int lane = tid & 31;
    const int wm   = wid >> 1;            // 0..3 (M dir, 32 rows)
    const int wn   = wid & 1;             // 0..1 (N dir, 64 cols)
    const int gid  = lane >> 2;           // 0..7
    const int tig  = lane & 3;            // 0..3

    // ldmatrix per-lane byte offsets (within a stage):
    // quadrants: lanes 0-7 rows +0..7 col 0; 8-15 rows +8..15 col 0;
    //            16-23 rows +0..7 col +8 halves; 24-31 rows +8..15 col +8.
    const int lrow = (lane & 7) + 8 * ((lane >> 3) & 1);
    const int lcol = (lane >> 4) * 4;              // u32
    const uint32_t aoff0 = ((wm * 32 + lrow) * SSTR + lcol) * 4;
    const uint32_t aoff1 = ((wm * 32 + 16 + lrow) * SSTR + lcol) * 4;
    uint32_t boff[4];
    #pragma unroll
    for (int jp = 0; jp < 4; ++jp)
        boff[jp] = (uint32_t)(AU32 + (wn * 64 + jp * 16 + lrow) * SSTR + lcol) * 4;

    float acc[2][8][4];
    #pragma unroll
    for (int i = 0; i < 2; ++i)
        #pragma unroll
        for (int j = 0; j < 8; ++j)
            #pragma unroll
            for (int p = 0; p < 4; ++p)
                acc[i][j][p] = 0.0f;

    FILL(0, 0);
    FILL(1, 1);

    int stg = 0;
    #pragma unroll 1
    for (int kt = 0; kt < NT; ++kt) {
        if (kt < NT - 1) cp_wait<1>(); else cp_wait<0>();
        __syncthreads();   // stage kt ready; all warps done with stage kt-1

        if (kt + 2 < NT) {
            int ns = stg + 2; if (ns >= STAGES) ns -= STAGES;
            FILL(kt + 2, ns);   // overwrites stage consumed at kt-1: safe
        }

        const uint32_t sb = smadr + stg * STAGE_U32 * 4;

        #pragma unroll
        for (int s = 0; s < 4; ++s) {    // four k=16 steps per tile
            const uint32_t ks = sb + s * 32;     // +8 u32 per step
            uint32_t a[2][4];
            ldsm_x4(a[0], ks + aoff0);
            ldsm_x4(a[1], ks + aoff1);
            #pragma unroll
            for (int jp = 0; jp < 4; ++jp) {
                uint32_t bv[4];          // {b0_j, b0_j+1, b1_j, b1_j+1}
                ldsm_x4(bv, ks + boff[jp]);
                mma_f16(acc[0][2 * jp],     a[0], bv[0], bv[2]);
                mma_f16(acc[1][2 * jp],     a[1], bv[0], bv[2]);
                mma_f16(acc[0][2 * jp + 1], a[0], bv[1], bv[3]);
                mma_f16(acc[1][2 * jp + 1], a[1], bv[1], bv[3]);
            }
        }

        ++stg; if (stg >= STAGES) stg -= STAGES;
    }

    // -------- epilogue: scale by precomputed inverse norms ----------------
    const float* invx = g_invnx + b * Tn + mcta;
    const float* invy = g_invny + b * Sn + ncta;
    float* C = out + (size_t)b * Tn * Sn + (size_t)mcta * Sn + ncta;

    #pragma unroll
    for (int i = 0; i < 2; ++i) {
        const int rA = wm * 32 + i * 16 + gid;
        const float sx0 = invx[rA];
        const float sx1 = invx[rA + 8];
        #pragma unroll
        for (int j = 0; j < 8; ++j) {
            const int c0 = wn * 64 + j * 8 + tig * 2;
            const float sy0 = invy[c0];
            const float sy1 = invy[c0 + 1];
            float2 w;
            w.x = acc[i][j][0] * sx0 * sy0;
            w.y = acc[i][j][1] * sx0 * sy1;
            *reinterpret_cast<float2*>(&C[(size_t)rA * Sn + c0]) = w;
            w.x = acc[i][j][2] * sx1 * sy0;
            w.y = acc[i][j][3] * sx1 * sy1;
            *reinterpret_cast<float2*>(&C[(size_t)(rA + 8) * Sn + c0]) = w;
        }
    }
}

extern "C" void kernel_launch(void* const* d_in, const int* in_sizes, int n_in,
                              void* d_out, int out_size) {
    const float* xs  = (const float*)d_in[0];   // (8, 4096, 512)
    const float* spk = (const float*)d_in[1];   // (8, 256, 512)
    float* out = (float*)d_out;                 // (8, 4096, 256)

    static bool attr_set = false;
    if (!attr_set) {
        cudaFuncSetAttribute(cos_gemm3,
                             cudaFuncAttributeMaxDynamicSharedMemorySize,
                             SMEM_TOTAL);
        attr_set = true;
    }

    {   // prep: 34816 row-warps, 8 warps per 256-thread block
        int blocks = (NX + NY + 7) / 8;
        cos_prep<<<blocks, 256>>>(xs, spk);
    }
    {
        dim3 grid(Tn / BM, Sn / BN, Bn);        // (32, 2, 8) = 512 CTAs
        cos_gemm3<<<grid, 256, SMEM_TOTAL>>>(out);
    }
}